// round 5
// baseline (speedup 1.0000x reference)
#include <cuda_runtime.h>
#include <cstdint>

// Modulated deformable conv 3x3, in_ch=out_ch=1, stride=1, pad=1, dil=1.
// H=W=512 hardcoded. R5: cp.async.bulk (UBLKCP) stages the streaming
// offset/mask operands through a 3-stage smem ring; gathers stay LDG/L1.

#define Hc 512
#define Wc 512
#define HWc (Hc * Wc)
#define TILE 1024              // pixels per block (contiguous)
#define NSTAGE 3
#define STAGE_BYTES (3 * TILE * 4)   // dy + dx + m = 12288

__device__ __forceinline__ uint32_t smem_u32(const void* p) {
    uint32_t a;
    asm("{ .reg .u64 t; cvta.to.shared.u64 t, %1; cvt.u32.u64 %0, t; }"
        : "=r"(a) : "l"(p));
    return a;
}

#define MBAR_INIT(addr, cnt) \
    asm volatile("mbarrier.init.shared.b64 [%0], %1;" :: "r"(addr), "r"(cnt) : "memory")
#define MBAR_EXPECT_TX(addr, bytes) \
    asm volatile("mbarrier.arrive.expect_tx.shared.b64 _, [%0], %1;" \
                 :: "r"(addr), "r"(bytes) : "memory")

__device__ __forceinline__ void mbar_wait_parity(uint32_t addr, uint32_t parity) {
    asm volatile(
        "{\n\t"
        ".reg .pred P;\n\t"
        "LAB_WAIT_%=:\n\t"
        "mbarrier.try_wait.parity.acquire.cta.shared::cta.b64 P, [%0], %1, 0x989680;\n\t"
        "@P bra.uni LAB_DONE_%=;\n\t"
        "bra.uni LAB_WAIT_%=;\n\t"
        "LAB_DONE_%=:\n\t"
        "}"
        :: "r"(addr), "r"(parity) : "memory");
}

__device__ __forceinline__ void bulk_cp(uint32_t dst_smem, const void* src_gmem,
                                        uint32_t bytes, uint32_t mbar) {
    asm volatile(
        "cp.async.bulk.shared::cluster.global.mbarrier::complete_tx::bytes "
        "[%0], [%1], %2, [%3];"
        :: "r"(dst_smem), "l"(src_gmem), "r"(bytes), "r"(mbar) : "memory");
}

__device__ __forceinline__ float bilin_sample(const float* __restrict__ img,
                                              float y, float x) {
    float y0f = floorf(y);
    float x0f = floorf(x);
    float wy = y - y0f;
    float wx = x - x0f;
    int y0 = (int)y0f;
    int x0 = (int)x0f;
    int base = (y0 << 9) + x0;   // W = 512
    bool vy0 = (unsigned)y0 < (unsigned)Hc;
    bool vy1 = (unsigned)(y0 + 1) < (unsigned)Hc;
    bool vx0 = (unsigned)x0 < (unsigned)Wc;
    bool vx1 = (unsigned)(x0 + 1) < (unsigned)Wc;
    float v00 = (vy0 && vx0) ? __ldg(img + base)          : 0.0f;
    float v01 = (vy0 && vx1) ? __ldg(img + base + 1)      : 0.0f;
    float v10 = (vy1 && vx0) ? __ldg(img + base + Wc)     : 0.0f;
    float v11 = (vy1 && vx1) ? __ldg(img + base + Wc + 1) : 0.0f;
    float top = fmaf(wx, v01 - v00, v00);
    float bot = fmaf(wx, v11 - v10, v10);
    return fmaf(wy, bot - top, top);
}

struct __align__(16) StageBuf {
    float dy[TILE];
    float dx[TILE];
    float m[TILE];
};

__global__ __launch_bounds__(256)
void dcn_kernel(const float* __restrict__ depth,
                const float* __restrict__ mask,
                const float* __restrict__ off,
                const float* __restrict__ w9,
                const float* __restrict__ bias,
                float* __restrict__ out,
                int B)
{
    __shared__ StageBuf stage[NSTAGE];
    __shared__ __align__(8) unsigned long long full_bar[NSTAGE];

    int tid = threadIdx.x;
    int bid = blockIdx.x;
    int b   = bid >> 8;                 // 256 blocks per image (HWc/TILE)
    int pixInImg = (bid & 255) * TILE;  // tile start within image

    const float* img   = depth + (size_t)b * HWc;
    const float* mbase = mask  + (size_t)b * 9  * HWc + pixInImg;
    const float* obase = off   + (size_t)b * 18 * HWc + pixInImg;

    uint32_t bar_addr[NSTAGE];
    #pragma unroll
    for (int s = 0; s < NSTAGE; s++) bar_addr[s] = smem_u32(&full_bar[s]);

    if (tid == 0) {
        #pragma unroll
        for (int s = 0; s < NSTAGE; s++) MBAR_INIT(bar_addr[s], 1);
    }
    __syncthreads();

    // Prologue: issue taps 0..2
    if (tid == 0) {
        #pragma unroll
        for (int t = 0; t < NSTAGE; t++) {
            MBAR_EXPECT_TX(bar_addr[t], STAGE_BYTES);
            bulk_cp(smem_u32(stage[t].dy), obase + (size_t)(2 * t)     * HWc, TILE * 4, bar_addr[t]);
            bulk_cp(smem_u32(stage[t].dx), obase + (size_t)(2 * t + 1) * HWc, TILE * 4, bar_addr[t]);
            bulk_cp(smem_u32(stage[t].m),  mbase + (size_t)t           * HWc, TILE * 4, bar_addr[t]);
        }
    }

    // Per-thread pixel group: 4 consecutive x pixels
    int p  = pixInImg + tid * 4;
    int iy = p >> 9;
    int ix = p & 511;

    float wreg[9];
    #pragma unroll
    for (int t = 0; t < 9; t++) wreg[t] = __ldg(w9 + t);

    float acc0 = 0.0f, acc1 = 0.0f, acc2 = 0.0f, acc3 = 0.0f;

    #pragma unroll
    for (int t = 0; t < 9; t++) {
        int s = t % NSTAGE;
        uint32_t parity = (t / NSTAGE) & 1;
        mbar_wait_parity(bar_addr[s], parity);

        float4 dy4 = *(const float4*)(stage[s].dy + tid * 4);
        float4 dx4 = *(const float4*)(stage[s].dx + tid * 4);
        float4 m4  = *(const float4*)(stage[s].m  + tid * 4);
        float  wt  = wreg[t];

        float ybase = (float)(iy - 1 + t / 3);
        float xbase = (float)(ix - 1 + t % 3);

        float sv;
        sv = bilin_sample(img, ybase + dy4.x, xbase + 0.0f + dx4.x);
        acc0 = fmaf(sv, m4.x * wt, acc0);
        sv = bilin_sample(img, ybase + dy4.y, xbase + 1.0f + dx4.y);
        acc1 = fmaf(sv, m4.y * wt, acc1);
        sv = bilin_sample(img, ybase + dy4.z, xbase + 2.0f + dx4.z);
        acc2 = fmaf(sv, m4.z * wt, acc2);
        sv = bilin_sample(img, ybase + dy4.w, xbase + 3.0f + dx4.w);
        acc3 = fmaf(sv, m4.w * wt, acc3);

        // All threads finished reading stage s for this round
        __syncthreads();

        // Refill the freed stage with tap t+3
        int tn = t + NSTAGE;
        if (tid == 0 && tn < 9) {
            MBAR_EXPECT_TX(bar_addr[s], STAGE_BYTES);
            bulk_cp(smem_u32(stage[s].dy), obase + (size_t)(2 * tn)     * HWc, TILE * 4, bar_addr[s]);
            bulk_cp(smem_u32(stage[s].dx), obase + (size_t)(2 * tn + 1) * HWc, TILE * 4, bar_addr[s]);
            bulk_cp(smem_u32(stage[s].m),  mbase + (size_t)tn           * HWc, TILE * 4, bar_addr[s]);
        }
    }

    float bv = __ldg(bias);
    float4 o;
    o.x = acc0 + bv;
    o.y = acc1 + bv;
    o.z = acc2 + bv;
    o.w = acc3 + bv;
    *(float4*)(out + (size_t)b * HWc + p) = o;
}

extern "C" void kernel_launch(void* const* d_in, const int* in_sizes, int n_in,
                              void* d_out, int out_size)
{
    const float* depth = (const float*)d_in[0];
    const float* mask  = (const float*)d_in[1];
    const float* off   = (const float*)d_in[2];
    const float* w9    = (const float*)d_in[3];
    const float* bias  = (const float*)d_in[4];
    float* out = (float*)d_out;

    int B = in_sizes[0] / HWc;
    int blocks = B * (HWc / TILE);   // 256 blocks per image
    dcn_kernel<<<blocks, 256>>>(depth, mask, off, w9, bias, out, B);
}

// round 6
// speedup vs baseline: 2.0948x; 2.0948x over previous
#include <cuda_runtime.h>
#include <cstdint>

// Modulated deformable conv 3x3, in_ch=out_ch=1, stride=1, pad=1, dil=1.
// H=W=512 hardcoded. R6: per-thread cp.async (LDGSTS) pipeline, depth 3.
// Each thread stages its own 48B of streaming operands per tap into smem;
// completion via cp.async.wait_group — no block barriers, no mbarriers.

#define Hc 512
#define Wc 512
#define HWc (Hc * Wc)
#define TILE 1024              // pixels per block (256 threads x 4 px)

__device__ __forceinline__ uint32_t smem_u32(const void* p) {
    uint32_t a;
    asm("{ .reg .u64 t; cvta.to.shared.u64 t, %1; cvt.u32.u64 %0, t; }"
        : "=r"(a) : "l"(p));
    return a;
}

#define CP_ASYNC_16(dst, src) \
    asm volatile("cp.async.cg.shared.global [%0], [%1], 16;" \
                 :: "r"(dst), "l"(src) : "memory")
#define CP_COMMIT() asm volatile("cp.async.commit_group;" ::: "memory")
#define CP_WAIT(n)  asm volatile("cp.async.wait_group %0;" :: "n"(n) : "memory")

__device__ __forceinline__ float bilin_sample(const float* __restrict__ img,
                                              float y, float x) {
    float y0f = floorf(y);
    float x0f = floorf(x);
    float wy = y - y0f;
    float wx = x - x0f;
    int y0 = (int)y0f;
    int x0 = (int)x0f;
    int base = (y0 << 9) + x0;   // W = 512
    bool vy0 = (unsigned)y0 < (unsigned)Hc;
    bool vy1 = (unsigned)(y0 + 1) < (unsigned)Hc;
    bool vx0 = (unsigned)x0 < (unsigned)Wc;
    bool vx1 = (unsigned)(x0 + 1) < (unsigned)Wc;
    float v00 = (vy0 && vx0) ? __ldg(img + base)          : 0.0f;
    float v01 = (vy0 && vx1) ? __ldg(img + base + 1)      : 0.0f;
    float v10 = (vy1 && vx0) ? __ldg(img + base + Wc)     : 0.0f;
    float v11 = (vy1 && vx1) ? __ldg(img + base + Wc + 1) : 0.0f;
    float top = fmaf(wx, v01 - v00, v00);
    float bot = fmaf(wx, v11 - v10, v10);
    return fmaf(wy, bot - top, top);
}

__global__ __launch_bounds__(256)
void dcn_kernel(const float* __restrict__ depth,
                const float* __restrict__ mask,
                const float* __restrict__ off,
                const float* __restrict__ w9,
                const float* __restrict__ bias,
                float* __restrict__ out,
                int B)
{
    // 3-stage per-thread staging buffers (SoA, float4 per thread per array)
    __shared__ __align__(16) float4 sdy[3][256];
    __shared__ __align__(16) float4 sdx[3][256];
    __shared__ __align__(16) float4 smk[3][256];

    int tid = threadIdx.x;
    int bid = blockIdx.x;
    int b   = bid >> 8;                 // 256 blocks per image (HWc/TILE)
    int pixInImg = (bid & 255) * TILE;  // tile start within image
    int p  = pixInImg + tid * 4;        // this thread's 4 consecutive px
    int iy = p >> 9;
    int ix = p & 511;

    const float* img  = depth + (size_t)b * HWc;
    const float* mptr = mask  + (size_t)b * 9  * HWc + p;
    const float* optr = off   + (size_t)b * 18 * HWc + p;

    // This thread's smem slot addresses per stage
    uint32_t a_dy[3], a_dx[3], a_m[3];
    #pragma unroll
    for (int s = 0; s < 3; s++) {
        a_dy[s] = smem_u32(&sdy[s][tid]);
        a_dx[s] = smem_u32(&sdx[s][tid]);
        a_m[s]  = smem_u32(&smk[s][tid]);
    }

    // Prologue: stage taps 0..2, one commit group per tap
    #pragma unroll
    for (int t = 0; t < 3; t++) {
        CP_ASYNC_16(a_dy[t], optr + (size_t)(2 * t)     * HWc);
        CP_ASYNC_16(a_dx[t], optr + (size_t)(2 * t + 1) * HWc);
        CP_ASYNC_16(a_m[t],  mptr + (size_t)t           * HWc);
        CP_COMMIT();
    }

    float wreg[9];
    #pragma unroll
    for (int t = 0; t < 9; t++) wreg[t] = __ldg(w9 + t);

    float acc0 = 0.0f, acc1 = 0.0f, acc2 = 0.0f, acc3 = 0.0f;

    #pragma unroll
    for (int t = 0; t < 9; t++) {
        int s = t % 3;

        // Oldest group (tap t) complete; 2 newer groups may remain in flight
        CP_WAIT(2);

        float4 dy4 = sdy[s][tid];
        float4 dx4 = sdx[s][tid];
        float4 m4  = smk[s][tid];

        // Refill freed stage with tap t+3 (this thread's own slots only; the
        // LDS reads above are already in flight before the LDGSTS writes land)
        int tn = t + 3;
        if (tn < 9) {
            CP_ASYNC_16(a_dy[s], optr + (size_t)(2 * tn)     * HWc);
            CP_ASYNC_16(a_dx[s], optr + (size_t)(2 * tn + 1) * HWc);
            CP_ASYNC_16(a_m[s],  mptr + (size_t)tn           * HWc);
        }
        CP_COMMIT();   // always one group per iteration (empty groups are legal)

        float wt = wreg[t];
        float ybase = (float)(iy - 1 + t / 3);
        float xbase = (float)(ix - 1 + t % 3);

        float sv;
        sv = bilin_sample(img, ybase + dy4.x, xbase + 0.0f + dx4.x);
        acc0 = fmaf(sv, m4.x * wt, acc0);
        sv = bilin_sample(img, ybase + dy4.y, xbase + 1.0f + dx4.y);
        acc1 = fmaf(sv, m4.y * wt, acc1);
        sv = bilin_sample(img, ybase + dy4.z, xbase + 2.0f + dx4.z);
        acc2 = fmaf(sv, m4.z * wt, acc2);
        sv = bilin_sample(img, ybase + dy4.w, xbase + 3.0f + dx4.w);
        acc3 = fmaf(sv, m4.w * wt, acc3);
    }

    float bv = __ldg(bias);
    float4 o;
    o.x = acc0 + bv;
    o.y = acc1 + bv;
    o.z = acc2 + bv;
    o.w = acc3 + bv;
    *(float4*)(out + (size_t)b * HWc + p) = o;
}

extern "C" void kernel_launch(void* const* d_in, const int* in_sizes, int n_in,
                              void* d_out, int out_size)
{
    const float* depth = (const float*)d_in[0];
    const float* mask  = (const float*)d_in[1];
    const float* off   = (const float*)d_in[2];
    const float* w9    = (const float*)d_in[3];
    const float* bias  = (const float*)d_in[4];
    float* out = (float*)d_out;

    int B = in_sizes[0] / HWc;
    int blocks = B * (HWc / TILE);   // 256 blocks per image
    dcn_kernel<<<blocks, 256>>>(depth, mask, off, w9, bias, out, B);
}

// round 7
// speedup vs baseline: 2.2402x; 1.0694x over previous
#include <cuda_runtime.h>
#include <cstdint>

// Modulated deformable conv 3x3, in_ch=out_ch=1, stride=1, pad=1, dil=1.
// H=W=512 hardcoded. R7: vertical gather layout (warp = 32 x-lanes, each
// thread 4 rows at its x -> small L1 gather footprint) + warp-cooperative
// cp.async staging of streaming operands (3 LDGSTS.128 per warp per tap,
// 4-stage ring, no block barriers).

#define Hc 512
#define Wc 512
#define HWc (Hc * Wc)
#define NS 4            // pipeline stages

__device__ __forceinline__ uint32_t smem_u32(const void* p) {
    uint32_t a;
    asm("{ .reg .u64 t; cvta.to.shared.u64 t, %1; cvt.u32.u64 %0, t; }"
        : "=r"(a) : "l"(p));
    return a;
}

#define CP_ASYNC_16(dst, src) \
    asm volatile("cp.async.cg.shared.global [%0], [%1], 16;" \
                 :: "r"(dst), "l"(src) : "memory")
#define CP_COMMIT() asm volatile("cp.async.commit_group;" ::: "memory")
#define CP_WAIT(n)  asm volatile("cp.async.wait_group %0;" :: "n"(n) : "memory")

__device__ __forceinline__ float bilin_sample(const float* __restrict__ img,
                                              float y, float x) {
    float y0f = floorf(y);
    float x0f = floorf(x);
    float wy = y - y0f;
    float wx = x - x0f;
    int y0 = (int)y0f;
    int x0 = (int)x0f;
    int base = (y0 << 9) + x0;   // W = 512
    bool vy0 = (unsigned)y0 < (unsigned)Hc;
    bool vy1 = (unsigned)(y0 + 1) < (unsigned)Hc;
    bool vx0 = (unsigned)x0 < (unsigned)Wc;
    bool vx1 = (unsigned)(x0 + 1) < (unsigned)Wc;
    float v00 = (vy0 && vx0) ? __ldg(img + base)          : 0.0f;
    float v01 = (vy0 && vx1) ? __ldg(img + base + 1)      : 0.0f;
    float v10 = (vy1 && vx0) ? __ldg(img + base + Wc)     : 0.0f;
    float v11 = (vy1 && vx1) ? __ldg(img + base + Wc + 1) : 0.0f;
    float top = fmaf(wx, v01 - v00, v00);
    float bot = fmaf(wx, v11 - v10, v10);
    return fmaf(wy, bot - top, top);
}

__global__ __launch_bounds__(256)
void dcn_kernel(const float* __restrict__ depth,
                const float* __restrict__ mask,
                const float* __restrict__ off,
                const float* __restrict__ w9,
                const float* __restrict__ bias,
                float* __restrict__ out,
                int B)
{
    // Per-warp staging: [stage][warp] slab of {dy,dx,m} x 4 rows x 32 px.
    // Chunk k (k=0..31) = row k>>3, 16B x-segment k&7.
    __shared__ __align__(16) float4 sdy[NS][8][32];
    __shared__ __align__(16) float4 sdx[NS][8][32];
    __shared__ __align__(16) float4 smk[NS][8][32];

    int tid  = threadIdx.x;
    int lane = tid & 31;
    int wrp  = tid >> 5;
    int bid  = blockIdx.x;
    int b    = bid >> 8;          // 256 blocks per image
    int rem  = bid & 255;
    int ys   = rem >> 1;          // 128 y-strips of 4 rows
    int xs   = rem & 1;           // 2 x-strips of 256 px
    int y0   = ys << 2;
    int xw   = (xs << 8) + (wrp << 5);   // warp x origin (mult of 32)
    int x    = xw + lane;

    const float* img   = depth + (size_t)b * HWc;
    // Warp-slab origins for streaming operands
    const float* osrc  = off  + (size_t)b * 18 * HWc + (y0 << 9) + xw;
    const float* msrc  = mask + (size_t)b * 9  * HWc + (y0 << 9) + xw;

    // Cooperative chunk source offset for this lane: row (lane>>3), seg (lane&7)
    int chunk_off = ((lane >> 3) << 9) + ((lane & 7) << 2);   // in floats

    // This lane's dst slots per stage
    uint32_t a_dy[NS], a_dx[NS], a_m[NS];
    #pragma unroll
    for (int s = 0; s < NS; s++) {
        a_dy[s] = smem_u32(&sdy[s][wrp][lane]);
        a_dx[s] = smem_u32(&sdx[s][wrp][lane]);
        a_m[s]  = smem_u32(&smk[s][wrp][lane]);
    }

    // Prologue: stage taps 0..NS-1, one commit group per tap
    #pragma unroll
    for (int t = 0; t < NS; t++) {
        CP_ASYNC_16(a_dy[t], osrc + (size_t)(2 * t)     * HWc + chunk_off);
        CP_ASYNC_16(a_dx[t], osrc + (size_t)(2 * t + 1) * HWc + chunk_off);
        CP_ASYNC_16(a_m[t],  msrc + (size_t)t           * HWc + chunk_off);
        CP_COMMIT();
    }

    float wreg[9];
    #pragma unroll
    for (int t = 0; t < 9; t++) wreg[t] = __ldg(w9 + t);

    float acc0 = 0.0f, acc1 = 0.0f, acc2 = 0.0f, acc3 = 0.0f;
    float xf = (float)x;

    #pragma unroll
    for (int t = 0; t < 9; t++) {
        int s = t % NS;

        CP_WAIT(NS - 1);        // tap t's group complete (this lane's copies)
        __syncwarp();           // ... and the whole warp's copies visible

        // Vertical consume: row j value at this lane = slab[j*32 + lane]
        const float* fdy = (const float*)&sdy[s][wrp][0];
        const float* fdx = (const float*)&sdx[s][wrp][0];
        const float* fm  = (const float*)&smk[s][wrp][0];
        float dy0 = fdy[lane],      dy1 = fdy[32 + lane],
              dy2 = fdy[64 + lane], dy3 = fdy[96 + lane];
        float dx0 = fdx[lane],      dx1 = fdx[32 + lane],
              dx2 = fdx[64 + lane], dx3 = fdx[96 + lane];
        float m0  = fm[lane],       m1  = fm[32 + lane],
              m2  = fm[64 + lane],  m3  = fm[96 + lane];

        __syncwarp();           // all lanes done reading stage s

        // Refill freed stage with tap t+NS (overlaps the gather math below)
        int tn = t + NS;
        if (tn < 9) {
            CP_ASYNC_16(a_dy[s], osrc + (size_t)(2 * tn)     * HWc + chunk_off);
            CP_ASYNC_16(a_dx[s], osrc + (size_t)(2 * tn + 1) * HWc + chunk_off);
            CP_ASYNC_16(a_m[s],  msrc + (size_t)tn           * HWc + chunk_off);
        }
        CP_COMMIT();            // one group per iteration, even if empty

        float wt = wreg[t];
        float ybase = (float)(y0 - 1 + t / 3);
        float xtap  = xf + (float)(t % 3 - 1);

        float sv;
        sv = bilin_sample(img, ybase + 0.0f + dy0, xtap + dx0);
        acc0 = fmaf(sv, m0 * wt, acc0);
        sv = bilin_sample(img, ybase + 1.0f + dy1, xtap + dx1);
        acc1 = fmaf(sv, m1 * wt, acc1);
        sv = bilin_sample(img, ybase + 2.0f + dy2, xtap + dx2);
        acc2 = fmaf(sv, m2 * wt, acc2);
        sv = bilin_sample(img, ybase + 3.0f + dy3, xtap + dx3);
        acc3 = fmaf(sv, m3 * wt, acc3);
    }

    float bv = __ldg(bias);
    float* optr = out + (size_t)b * HWc + (y0 << 9) + x;
    optr[0 * Wc] = acc0 + bv;
    optr[1 * Wc] = acc1 + bv;
    optr[2 * Wc] = acc2 + bv;
    optr[3 * Wc] = acc3 + bv;
}

extern "C" void kernel_launch(void* const* d_in, const int* in_sizes, int n_in,
                              void* d_out, int out_size)
{
    const float* depth = (const float*)d_in[0];
    const float* mask  = (const float*)d_in[1];
    const float* off   = (const float*)d_in[2];
    const float* w9    = (const float*)d_in[3];
    const float* bias  = (const float*)d_in[4];
    float* out = (float*)d_out;

    int B = in_sizes[0] / HWc;
    int blocks = B * 256;       // 256 blocks per 512x512 image
    dcn_kernel<<<blocks, 256>>>(depth, mask, off, w9, bias, out, B);
}

// round 8
// speedup vs baseline: 2.3373x; 1.0433x over previous
#include <cuda_runtime.h>
#include <cstdint>

// Modulated deformable conv 3x3, in_ch=out_ch=1, stride=1, pad=1, dil=1.
// H=W=512 hardcoded. R8: 2 rows per thread (low reg pressure -> 5 CTAs/SM),
// vertical gather layout, warp-cooperative cp.async staging (6-stage ring,
// 1.5 LDGSTS per warp-tap), no block barriers.

#define Hc 512
#define Wc 512
#define HWc (Hc * Wc)
#define NS 6            // pipeline stages

__device__ __forceinline__ uint32_t smem_u32(const void* p) {
    uint32_t a;
    asm("{ .reg .u64 t; cvta.to.shared.u64 t, %1; cvt.u32.u64 %0, t; }"
        : "=r"(a) : "l"(p));
    return a;
}

#define CP_ASYNC_16(dst, src) \
    asm volatile("cp.async.cg.shared.global [%0], [%1], 16;" \
                 :: "r"(dst), "l"(src) : "memory")
#define CP_COMMIT() asm volatile("cp.async.commit_group;" ::: "memory")
#define CP_WAIT(n)  asm volatile("cp.async.wait_group %0;" :: "n"(n) : "memory")

__device__ __forceinline__ float bilin_sample(const float* __restrict__ img,
                                              float y, float x) {
    float y0f = floorf(y);
    float x0f = floorf(x);
    float wy = y - y0f;
    float wx = x - x0f;
    int y0 = (int)y0f;
    int x0 = (int)x0f;
    int base = (y0 << 9) + x0;   // W = 512
    bool vy0 = (unsigned)y0 < (unsigned)Hc;
    bool vy1 = (unsigned)(y0 + 1) < (unsigned)Hc;
    bool vx0 = (unsigned)x0 < (unsigned)Wc;
    bool vx1 = (unsigned)(x0 + 1) < (unsigned)Wc;
    float v00 = (vy0 && vx0) ? __ldg(img + base)          : 0.0f;
    float v01 = (vy0 && vx1) ? __ldg(img + base + 1)      : 0.0f;
    float v10 = (vy1 && vx0) ? __ldg(img + base + Wc)     : 0.0f;
    float v11 = (vy1 && vx1) ? __ldg(img + base + Wc + 1) : 0.0f;
    float top = fmaf(wx, v01 - v00, v00);
    float bot = fmaf(wx, v11 - v10, v10);
    return fmaf(wy, bot - top, top);
}

__global__ __launch_bounds__(256, 5)
void dcn_kernel(const float* __restrict__ depth,
                const float* __restrict__ mask,
                const float* __restrict__ off,
                const float* __restrict__ w9,
                const float* __restrict__ bias,
                float* __restrict__ out,
                int B)
{
    // Per-warp slab per stage: dy[64] dx[64] m[64] floats (2 rows x 32 px).
    __shared__ __align__(16) float slab[NS][8][192];

    int tid  = threadIdx.x;
    int lane = tid & 31;
    int wrp  = tid >> 5;
    int bid  = blockIdx.x;
    int b    = bid >> 9;          // 512 blocks per image
    int rem  = bid & 511;
    int ys   = rem >> 1;          // 256 y-strips of 2 rows
    int xs   = rem & 1;           // 2 x-strips of 256 px
    int y0   = ys << 1;
    int xw   = (xs << 8) + (wrp << 5);   // warp x origin
    int x    = xw + lane;

    const float* img   = depth + (size_t)b * HWc;
    const float* obase = off   + (size_t)b * 18 * HWc + (y0 << 9) + xw;
    const float* mbase = mask  + (size_t)b * 9  * HWc + (y0 << 9) + xw;

    // Cooperative copy mapping:
    //  instrA (all 32 lanes): arr = lane>>4 (0=dy plane 2t, 1=dx plane 2t+1),
    //    cc = lane&15 -> row cc>>3, 16B segment cc&7.
    //  instrB (lanes 0..15): mask plane t, chunk = lane.
    int arr  = lane >> 4;
    int cc   = lane & 15;
    int coff = ((cc >> 3) << 9) + ((cc & 7) << 2);       // floats
    int moff = ((lane >> 3) << 9) + ((lane & 7) << 2);   // floats (lane<16)

    uint32_t adst[NS], bdst[NS];
    #pragma unroll
    for (int s = 0; s < NS; s++) {
        uint32_t base = smem_u32(&slab[s][wrp][0]);
        adst[s] = base + lane * 16;          // dy(64f)+dx(64f) = 512B
        bdst[s] = base + 512 + lane * 16;    // m(64f) = 256B (lanes<16)
    }

    // Prologue: stage taps 0..NS-1, one commit group per tap
    #pragma unroll
    for (int t = 0; t < NS; t++) {
        CP_ASYNC_16(adst[t], obase + (size_t)(2 * t + arr) * HWc + coff);
        if (lane < 16)
            CP_ASYNC_16(bdst[t], mbase + (size_t)t * HWc + moff);
        CP_COMMIT();
    }

    float wreg[9];
    #pragma unroll
    for (int t = 0; t < 9; t++) wreg[t] = __ldg(w9 + t);

    float acc0 = 0.0f, acc1 = 0.0f;
    float xf = (float)x;

    #pragma unroll
    for (int t = 0; t < 9; t++) {
        int s = t % NS;

        CP_WAIT(NS - 1);        // tap t's group complete
        __syncwarp();           // whole warp's chunks visible

        const float* f = &slab[s][wrp][0];
        float dy0 = f[lane],       dy1 = f[32 + lane];
        float dx0 = f[64 + lane],  dx1 = f[96 + lane];
        float m0  = f[128 + lane], m1  = f[160 + lane];

        __syncwarp();           // all lanes done reading stage s

        int tn = t + NS;
        if (tn < 9) {
            CP_ASYNC_16(adst[s], obase + (size_t)(2 * tn + arr) * HWc + coff);
            if (lane < 16)
                CP_ASYNC_16(bdst[s], mbase + (size_t)tn * HWc + moff);
        }
        CP_COMMIT();            // one group per iteration (empty ok)

        float wt = wreg[t];
        float ybase = (float)(y0 - 1 + t / 3);
        float xtap  = xf + (float)(t % 3 - 1);

        float sv;
        sv = bilin_sample(img, ybase + 0.0f + dy0, xtap + dx0);
        acc0 = fmaf(sv, m0 * wt, acc0);
        sv = bilin_sample(img, ybase + 1.0f + dy1, xtap + dx1);
        acc1 = fmaf(sv, m1 * wt, acc1);
    }

    float bv = __ldg(bias);
    float* optr = out + (size_t)b * HWc + (y0 << 9) + x;
    optr[0]  = acc0 + bv;
    optr[Wc] = acc1 + bv;
}

extern "C" void kernel_launch(void* const* d_in, const int* in_sizes, int n_in,
                              void* d_out, int out_size)
{
    const float* depth = (const float*)d_in[0];
    const float* mask  = (const float*)d_in[1];
    const float* off   = (const float*)d_in[2];
    const float* w9    = (const float*)d_in[3];
    const float* bias  = (const float*)d_in[4];
    float* out = (float*)d_out;

    int B = in_sizes[0] / HWc;
    int blocks = B * 512;       // 512 blocks per 512x512 image
    dcn_kernel<<<blocks, 256>>>(depth, mask, off, w9, bias, out, B);
}